// round 10
// baseline (speedup 1.0000x reference)
#include <cuda_runtime.h>
#include <cuda_bf16.h>
#include <math.h>
#include <stdint.h>

#define NN 50000
#define EE 800000
#define IN_DIM 128
#define HH 4
#define NEG_SLOPE 0.2f
#define NBLK_SCAN 196
#define MTILE 128
#define NCTA_GEMM 391
#define TS 136
#define TILE_U16 (128 * TS)
#define TILE_B (TILE_U16 * 2)
#define HPSTRIDE 132
#define NTHR 512

// ---------------- scratch ----------------
__device__ float g_feat[(size_t)NN * IN_DIM];
__device__ float g_el[NN * HH];
__device__ float g_er[NN * HH];
__device__ float g_hg[(size_t)NN * IN_DIM];
__device__ float g_gate[(size_t)NN * IN_DIM];   // ctx @ Wg2 partial
__device__ int   g_cnt[NN];
__device__ int   g_off[NN];
__device__ int   g_cur[NN];
__device__ int   g_esrc[EE];
__device__ int   g_bsum[256];
__device__ __align__(16) unsigned short g_WfcT[2 * TILE_U16];
__device__ __align__(16) unsigned short g_WpT[2 * TILE_U16];
__device__ __align__(16) unsigned short g_WgT[4 * TILE_U16];

// ---------------- helpers ----------------
__device__ __forceinline__ unsigned short bfb(__nv_bfloat16 v) {
    return *reinterpret_cast<unsigned short*>(&v);
}
__device__ __forceinline__ void split2(float x0, float x1, uint32_t& hi, uint32_t& lo) {
    __nv_bfloat16 h0 = __float2bfloat16(x0), h1 = __float2bfloat16(x1);
    __nv_bfloat16 l0 = __float2bfloat16(x0 - __bfloat162float(h0));
    __nv_bfloat16 l1 = __float2bfloat16(x1 - __bfloat162float(h1));
    hi = (uint32_t)bfb(h0) | ((uint32_t)bfb(h1) << 16);
    lo = (uint32_t)bfb(l0) | ((uint32_t)bfb(l1) << 16);
}
__device__ __forceinline__ void hmma(float* c, uint32_t a0, uint32_t a1, uint32_t a2, uint32_t a3,
                                     uint32_t b0, uint32_t b1) {
    asm volatile(
        "mma.sync.aligned.m16n8k16.row.col.f32.bf16.bf16.f32 "
        "{%0,%1,%2,%3}, {%4,%5,%6,%7}, {%8,%9}, {%0,%1,%2,%3};"
        : "+f"(c[0]), "+f"(c[1]), "+f"(c[2]), "+f"(c[3])
        : "r"(a0), "r"(a1), "r"(a2), "r"(a3), "r"(b0), "r"(b1));
}

template <int NT>
__device__ __forceinline__ void gemm_tile(float acc[2][NT][4],
    const uint32_t* Ahi, const uint32_t* Alo,
    const uint32_t* Bhi, const uint32_t* Blo,
    int m0, int n0, int g, int t) {
#pragma unroll
    for (int ks = 0; ks < 8; ks++) {
        int k0 = ks * 16;
        uint32_t ah[2][4], al[2][4];
#pragma unroll
        for (int mt = 0; mt < 2; mt++) {
            int r = m0 + mt * 16 + g;
            int i0 = (r * TS + k0 + 2 * t) >> 1;
            int i1 = ((r + 8) * TS + k0 + 2 * t) >> 1;
            ah[mt][0] = Ahi[i0]; ah[mt][1] = Ahi[i1];
            ah[mt][2] = Ahi[i0 + 4]; ah[mt][3] = Ahi[i1 + 4];
            al[mt][0] = Alo[i0]; al[mt][1] = Alo[i1];
            al[mt][2] = Alo[i0 + 4]; al[mt][3] = Alo[i1 + 4];
        }
#pragma unroll
        for (int nt = 0; nt < NT; nt++) {
            int c = n0 + nt * 8 + g;
            int bi = (c * TS + k0 + 2 * t) >> 1;
            uint32_t bh0 = Bhi[bi], bh1 = Bhi[bi + 4];
            uint32_t bl0 = Blo[bi], bl1 = Blo[bi + 4];
#pragma unroll
            for (int mt = 0; mt < 2; mt++) {
                hmma(acc[mt][nt], ah[mt][0], ah[mt][1], ah[mt][2], ah[mt][3], bh0, bh1);
                hmma(acc[mt][nt], ah[mt][0], ah[mt][1], ah[mt][2], ah[mt][3], bl0, bl1);
                hmma(acc[mt][nt], al[mt][0], al[mt][1], al[mt][2], al[mt][3], bh0, bh1);
            }
        }
    }
}

__device__ __forceinline__ void fill_A(unsigned short* Ahi, unsigned short* Alo,
                                       const float* __restrict__ src, long nodebase,
                                       int tid) {
    int m = tid >> 2, q = tid & 3;
    long node = nodebase + m;
    const float* row = src + node * IN_DIM + q * 32;
    uint32_t* H = (uint32_t*)Ahi;
    uint32_t* L = (uint32_t*)Alo;
#pragma unroll
    for (int k4 = 0; k4 < 32; k4 += 4) {
        float4 v = make_float4(0.f, 0.f, 0.f, 0.f);
        if (node < NN) v = *(const float4*)(row + k4);
        uint32_t h01, l01, h23, l23;
        split2(v.x, v.y, h01, l01);
        split2(v.z, v.w, h23, l23);
        int idx = (m * TS + q * 32 + k4) >> 1;
        H[idx] = h01; H[idx + 1] = h23;
        L[idx] = l01; L[idx + 1] = l23;
    }
}

__device__ __forceinline__ void copy_B(unsigned short* dst, const unsigned short* src, int tid) {
    const uint4* s = (const uint4*)src;
    uint4* d = (uint4*)dst;
#pragma unroll
    for (int i = tid; i < 2 * TILE_B / 16; i += NTHR) d[i] = s[i];
}

// ---------------- small kernels ----------------
__global__ void k_init() {
    int i = blockIdx.x * blockDim.x + threadIdx.x;
    if (i < NN) { g_cnt[i] = 0; g_cur[i] = 0; }
}

__global__ void k_hist(const int* __restrict__ dst) {
    int e = blockIdx.x * blockDim.x + threadIdx.x;
    if (e < EE) atomicAdd(&g_cnt[dst[e]], 1);
}

__global__ void k_prepw(const float* __restrict__ Wfc, const float* __restrict__ Wp,
                        const float* __restrict__ Wg) {
    int id = blockIdx.x * 256 + threadIdx.x;
    if (id < 16384) {
        int n = id >> 7, k = id & 127;
        float w = Wfc[k * 128 + n];
        __nv_bfloat16 hi = __float2bfloat16(w);
        __nv_bfloat16 lo = __float2bfloat16(w - __bfloat162float(hi));
        g_WfcT[n * TS + k] = bfb(hi);
        g_WfcT[TILE_U16 + n * TS + k] = bfb(lo);
    } else if (id < 32768) {
        int e = id - 16384;
        int n = e >> 7, k = e & 127;
        float w = Wp[k * 128 + n];
        __nv_bfloat16 hi = __float2bfloat16(w);
        __nv_bfloat16 lo = __float2bfloat16(w - __bfloat162float(hi));
        g_WpT[n * TS + k] = bfb(hi);
        g_WpT[TILE_U16 + n * TS + k] = bfb(lo);
    } else {
        int e = id - 32768;
        int n = e & 127, k = e >> 7;
        float w = Wg[k * 128 + n];
        int stage = k >> 7, kk = k & 127;
        __nv_bfloat16 hi = __float2bfloat16(w);
        __nv_bfloat16 lo = __float2bfloat16(w - __bfloat162float(hi));
        g_WgT[stage * 2 * TILE_U16 + n * TS + kk] = bfb(hi);
        g_WgT[stage * 2 * TILE_U16 + TILE_U16 + n * TS + kk] = bfb(lo);
    }
}

// ---------------- feat = h @ W_fc, fused el/er ----------------
__global__ void __launch_bounds__(NTHR, 1) k_feat_tc(const float* __restrict__ h,
                                                     const float* __restrict__ al,
                                                     const float* __restrict__ ar) {
    extern __shared__ __align__(16) unsigned short sm[];
    unsigned short* Ahi = sm;
    unsigned short* Alo = sm + TILE_U16;
    unsigned short* Bt  = sm + 2 * TILE_U16;
    int tid = threadIdx.x, wid = tid >> 5, lane = tid & 31;
    int g = lane >> 2, t = lane & 3;
    long nodebase = (long)blockIdx.x * MTILE;

    fill_A(Ahi, Alo, h, nodebase, tid);
    copy_B(Bt, g_WfcT, tid);
    __syncthreads();

    float acc[2][4][4];
#pragma unroll
    for (int a = 0; a < 2; a++)
#pragma unroll
        for (int b = 0; b < 4; b++)
#pragma unroll
            for (int c = 0; c < 4; c++) acc[a][b][c] = 0.f;

    int m0 = (wid >> 2) * 32, n0 = (wid & 3) * 32;
    gemm_tile<4>(acc, (const uint32_t*)Ahi, (const uint32_t*)Alo,
                 (const uint32_t*)Bt, (const uint32_t*)(Bt + TILE_U16), m0, n0, g, t);

    int head = wid & 3;
    float pl[4] = {0.f, 0.f, 0.f, 0.f};
    float pr[4] = {0.f, 0.f, 0.f, 0.f};
#pragma unroll
    for (int nt = 0; nt < 4; nt++) {
        int col = n0 + nt * 8 + 2 * t;
        float a0 = __ldg(&al[col]), a1 = __ldg(&al[col + 1]);
        float b0 = __ldg(&ar[col]), b1 = __ldg(&ar[col + 1]);
#pragma unroll
        for (int mt = 0; mt < 2; mt++) {
            pl[2 * mt]     += acc[mt][nt][0] * a0 + acc[mt][nt][1] * a1;
            pl[2 * mt + 1] += acc[mt][nt][2] * a0 + acc[mt][nt][3] * a1;
            pr[2 * mt]     += acc[mt][nt][0] * b0 + acc[mt][nt][1] * b1;
            pr[2 * mt + 1] += acc[mt][nt][2] * b0 + acc[mt][nt][3] * b1;
        }
    }
#pragma unroll
    for (int off = 1; off <= 2; off <<= 1) {
#pragma unroll
        for (int i = 0; i < 4; i++) {
            pl[i] += __shfl_xor_sync(0xffffffffu, pl[i], off);
            pr[i] += __shfl_xor_sync(0xffffffffu, pr[i], off);
        }
    }
    if (t == 0) {
#pragma unroll
        for (int mt = 0; mt < 2; mt++) {
            long r0 = nodebase + m0 + mt * 16 + g;
            long r1 = r0 + 8;
            if (r0 < NN) { g_el[r0 * HH + head] = pl[2 * mt];     g_er[r0 * HH + head] = pr[2 * mt]; }
            if (r1 < NN) { g_el[r1 * HH + head] = pl[2 * mt + 1]; g_er[r1 * HH + head] = pr[2 * mt + 1]; }
        }
    }

#pragma unroll
    for (int mt = 0; mt < 2; mt++) {
        long r0 = nodebase + m0 + mt * 16 + g;
        long r1 = r0 + 8;
#pragma unroll
        for (int nt = 0; nt < 4; nt++) {
            int col = n0 + nt * 8 + 2 * t;
            if (r0 < NN) *(float2*)&g_feat[r0 * IN_DIM + col] = make_float2(acc[mt][nt][0], acc[mt][nt][1]);
            if (r1 < NN) *(float2*)&g_feat[r1 * IN_DIM + col] = make_float2(acc[mt][nt][2], acc[mt][nt][3]);
        }
    }
}

// ---------------- ctxg = ctx @ Wg2^T (gate partial) ----------------
__global__ void __launch_bounds__(NTHR, 1) k_ctxg(const float* __restrict__ ctx) {
    extern __shared__ __align__(16) unsigned short sm[];
    unsigned short* Ahi = sm;
    unsigned short* Alo = sm + TILE_U16;
    unsigned short* Bt  = sm + 2 * TILE_U16;
    int tid = threadIdx.x, wid = tid >> 5, lane = tid & 31;
    int g = lane >> 2, t = lane & 3;
    long nodebase = (long)blockIdx.x * MTILE;

    fill_A(Ahi, Alo, ctx, nodebase, tid);
    copy_B(Bt, g_WgT + 2 * TILE_U16, tid);
    __syncthreads();

    float acc[2][4][4];
#pragma unroll
    for (int a = 0; a < 2; a++)
#pragma unroll
        for (int b = 0; b < 4; b++)
#pragma unroll
            for (int c = 0; c < 4; c++) acc[a][b][c] = 0.f;

    int m0 = (wid >> 2) * 32, n0 = (wid & 3) * 32;
    gemm_tile<4>(acc, (const uint32_t*)Ahi, (const uint32_t*)Alo,
                 (const uint32_t*)Bt, (const uint32_t*)(Bt + TILE_U16), m0, n0, g, t);

#pragma unroll
    for (int mt = 0; mt < 2; mt++) {
        long r0 = nodebase + m0 + mt * 16 + g;
        long r1 = r0 + 8;
#pragma unroll
        for (int nt = 0; nt < 4; nt++) {
            int col = n0 + nt * 8 + 2 * t;
            if (r0 < NN) *(float2*)&g_gate[r0 * IN_DIM + col] = make_float2(acc[mt][nt][0], acc[mt][nt][1]);
            if (r1 < NN) *(float2*)&g_gate[r1 * IN_DIM + col] = make_float2(acc[mt][nt][2], acc[mt][nt][3]);
        }
    }
}

// ---------------- scans / scatter ----------------
__global__ void k_scan1() {
    __shared__ int s[256];
    int i = blockIdx.x * 256 + threadIdx.x;
    int v = (i < NN) ? g_cnt[i] : 0;
    s[threadIdx.x] = v;
    __syncthreads();
#pragma unroll
    for (int off = 1; off < 256; off <<= 1) {
        int tv = (threadIdx.x >= off) ? s[threadIdx.x - off] : 0;
        __syncthreads();
        s[threadIdx.x] += tv;
        __syncthreads();
    }
    if (i < NN) g_off[i] = s[threadIdx.x] - v;
    if (threadIdx.x == 255) g_bsum[blockIdx.x] = s[255];
}

__global__ void k_scan2() {
    __shared__ int s[256];
    int t = threadIdx.x;
    int v = (t < NBLK_SCAN) ? g_bsum[t] : 0;
    s[t] = v;
    __syncthreads();
#pragma unroll
    for (int off = 1; off < 256; off <<= 1) {
        int tv = (t >= off) ? s[t - off] : 0;
        __syncthreads();
        s[t] += tv;
        __syncthreads();
    }
    if (t < NBLK_SCAN) g_bsum[t] = s[t] - v;
}

__global__ void k_scatter(const int* __restrict__ src, const int* __restrict__ dst) {
    int e = blockIdx.x * blockDim.x + threadIdx.x;
    if (e >= EE) return;
    int d = dst[e];
    int pos = atomicAdd(&g_cur[d], 1);
    g_esrc[g_off[d] + g_bsum[d >> 8] + pos] = src[e];
}

// ---------------- aggregate: warp per node, 4 edges/iter ----------------
__global__ void k_agg(const float* __restrict__ bgat) {
    int gw = (blockIdx.x * blockDim.x + threadIdx.x) >> 5;
    if (gw >= NN) return;
    int lane = threadIdx.x & 31;
    int beg = g_off[gw] + g_bsum[gw >> 8];
    int end = beg + g_cnt[gw];
    float er_h = (lane < HH) ? g_er[gw * HH + lane] : 0.f;
    float er16 = __shfl_sync(0xffffffffu, er_h, lane & 3);
    int hd = lane >> 3;
    float4 acc = make_float4(0.f, 0.f, 0.f, 0.f);
    float dsum = 0.f;
    int i = beg;
    for (; i + 3 < end; i += 4) {
        int s0 = __ldg(&g_esrc[i]);
        int s1 = __ldg(&g_esrc[i + 1]);
        int s2 = __ldg(&g_esrc[i + 2]);
        int s3 = __ldg(&g_esrc[i + 3]);
        float a = 0.f;
        if (lane < 16) {
            int eix = lane >> 2;
            int sx = (eix == 0) ? s0 : (eix == 1) ? s1 : (eix == 2) ? s2 : s3;
            float e = g_el[sx * HH + (lane & 3)] + er16;
            e = (e > 0.f) ? e : NEG_SLOPE * e;
            a = __expf(e);
        }
        float a0 = __shfl_sync(0xffffffffu, a, hd);
        float a1 = __shfl_sync(0xffffffffu, a, 4 + hd);
        float a2 = __shfl_sync(0xffffffffu, a, 8 + hd);
        float a3 = __shfl_sync(0xffffffffu, a, 12 + hd);
        dsum += (a0 + a1) + (a2 + a3);
        float4 f0 = ((const float4*)g_feat)[(size_t)s0 * (IN_DIM / 4) + lane];
        float4 f1 = ((const float4*)g_feat)[(size_t)s1 * (IN_DIM / 4) + lane];
        float4 f2 = ((const float4*)g_feat)[(size_t)s2 * (IN_DIM / 4) + lane];
        float4 f3 = ((const float4*)g_feat)[(size_t)s3 * (IN_DIM / 4) + lane];
        acc.x = fmaf(f0.x, a0, acc.x); acc.y = fmaf(f0.y, a0, acc.y);
        acc.z = fmaf(f0.z, a0, acc.z); acc.w = fmaf(f0.w, a0, acc.w);
        acc.x = fmaf(f1.x, a1, acc.x); acc.y = fmaf(f1.y, a1, acc.y);
        acc.z = fmaf(f1.z, a1, acc.z); acc.w = fmaf(f1.w, a1, acc.w);
        acc.x = fmaf(f2.x, a2, acc.x); acc.y = fmaf(f2.y, a2, acc.y);
        acc.z = fmaf(f2.z, a2, acc.z); acc.w = fmaf(f2.w, a2, acc.w);
        acc.x = fmaf(f3.x, a3, acc.x); acc.y = fmaf(f3.y, a3, acc.y);
        acc.z = fmaf(f3.z, a3, acc.z); acc.w = fmaf(f3.w, a3, acc.w);
    }
    for (; i < end; i++) {
        int s0 = __ldg(&g_esrc[i]);
        float a = 0.f;
        if (lane < 4) {
            float e = g_el[s0 * HH + lane] + er16;
            e = (e > 0.f) ? e : NEG_SLOPE * e;
            a = __expf(e);
        }
        float a0 = __shfl_sync(0xffffffffu, a, hd);
        dsum += a0;
        float4 f0 = ((const float4*)g_feat)[(size_t)s0 * (IN_DIM / 4) + lane];
        acc.x = fmaf(f0.x, a0, acc.x); acc.y = fmaf(f0.y, a0, acc.y);
        acc.z = fmaf(f0.z, a0, acc.z); acc.w = fmaf(f0.w, a0, acc.w);
    }
    float inv = (dsum > 0.f) ? (1.f / dsum) : 0.f;
    float4 b = ((const float4*)bgat)[lane];
    float4 o;
    o.x = acc.x * inv + b.x; o.y = acc.y * inv + b.y;
    o.z = acc.z * inv + b.z; o.w = acc.w * inv + b.w;
    o.x = (o.x > 0.f) ? o.x : expm1f(o.x);
    o.y = (o.y > 0.f) ? o.y : expm1f(o.y);
    o.z = (o.z > 0.f) ? o.z : expm1f(o.z);
    o.w = (o.w > 0.f) ? o.w : expm1f(o.w);
    ((float4*)g_hg)[(size_t)gw * (IN_DIM / 4) + lane] = o;
}

// ---------------- node: proj + gate(partial) + blend ----------------
__global__ void __launch_bounds__(NTHR, 1) k_node_tc(
    const float* __restrict__ ctx, const float* __restrict__ bp,
    const float* __restrict__ bg, float* __restrict__ out) {
    extern __shared__ __align__(16) unsigned short sm[];
    unsigned short* Ahi = sm;
    unsigned short* Alo = sm + TILE_U16;
    unsigned short* Bt  = sm + 2 * TILE_U16;
    float* hpbuf = (float*)(sm + 4 * TILE_U16);
    int tid = threadIdx.x, wid = tid >> 5, lane = tid & 31;
    int g = lane >> 2, t = lane & 3;
    long nodebase = (long)blockIdx.x * MTILE;
    int m0 = (wid >> 2) * 32, n0 = (wid & 3) * 32;

    // phase 1: hp = hg @ Wp^T
    fill_A(Ahi, Alo, g_hg, nodebase, tid);
    copy_B(Bt, g_WpT, tid);
    __syncthreads();

    float acc[2][4][4];
#pragma unroll
    for (int a = 0; a < 2; a++)
#pragma unroll
        for (int b = 0; b < 4; b++)
#pragma unroll
            for (int c = 0; c < 4; c++) acc[a][b][c] = 0.f;

    gemm_tile<4>(acc, (const uint32_t*)Ahi, (const uint32_t*)Alo,
                 (const uint32_t*)Bt, (const uint32_t*)(Bt + TILE_U16), m0, n0, g, t);
    __syncthreads();

    {
        uint32_t* H = (uint32_t*)Ahi;
        uint32_t* L = (uint32_t*)Alo;
#pragma unroll
        for (int nt = 0; nt < 4; nt++) {
            int col = n0 + nt * 8 + 2 * t;
            float2 bpv = *(const float2*)&bp[col];
#pragma unroll
            for (int mt = 0; mt < 2; mt++) {
                int r0 = m0 + mt * 16 + g, r1 = r0 + 8;
                float h0 = acc[mt][nt][0] + bpv.x, h1 = acc[mt][nt][1] + bpv.y;
                float h2 = acc[mt][nt][2] + bpv.x, h3 = acc[mt][nt][3] + bpv.y;
                *(float2*)&hpbuf[r0 * HPSTRIDE + col] = make_float2(h0, h1);
                *(float2*)&hpbuf[r1 * HPSTRIDE + col] = make_float2(h2, h3);
                uint32_t hi, lo;
                split2(h0, h1, hi, lo);
                H[(r0 * TS + col) >> 1] = hi;
                L[(r0 * TS + col) >> 1] = lo;
                split2(h2, h3, hi, lo);
                H[(r1 * TS + col) >> 1] = hi;
                L[(r1 * TS + col) >> 1] = lo;
            }
        }
    }
    copy_B(Bt, g_WgT, tid);
    __syncthreads();

    // phase 2: gate = hp @ Wg1^T (ctx part comes from g_gate)
#pragma unroll
    for (int a = 0; a < 2; a++)
#pragma unroll
        for (int b = 0; b < 4; b++)
#pragma unroll
            for (int c = 0; c < 4; c++) acc[a][b][c] = 0.f;
    gemm_tile<4>(acc, (const uint32_t*)Ahi, (const uint32_t*)Alo,
                 (const uint32_t*)Bt, (const uint32_t*)(Bt + TILE_U16), m0, n0, g, t);

    // epilogue: add gate partial, sigmoid, blend
#pragma unroll
    for (int nt = 0; nt < 4; nt++) {
        int col = n0 + nt * 8 + 2 * t;
        float2 bgv = *(const float2*)&bg[col];
#pragma unroll
        for (int mt = 0; mt < 2; mt++) {
            int lr0 = m0 + mt * 16 + g, lr1 = lr0 + 8;
            long r0 = nodebase + lr0, r1 = nodebase + lr1;
            if (r0 < NN) {
                float2 cv = *(const float2*)&ctx[r0 * IN_DIM + col];
                float2 gv = *(const float2*)&g_gate[r0 * IN_DIM + col];
                float s0 = 1.f / (1.f + __expf(-(acc[mt][nt][0] + gv.x + bgv.x)));
                float s1 = 1.f / (1.f + __expf(-(acc[mt][nt][1] + gv.y + bgv.y)));
                float2 hv = *(const float2*)&hpbuf[lr0 * HPSTRIDE + col];
                *(float2*)&out[r0 * IN_DIM + col] =
                    make_float2(s0 * hv.x + (1.f - s0) * cv.x, s1 * hv.y + (1.f - s1) * cv.y);
            }
            if (r1 < NN) {
                float2 cv = *(const float2*)&ctx[r1 * IN_DIM + col];
                float2 gv = *(const float2*)&g_gate[r1 * IN_DIM + col];
                float s2 = 1.f / (1.f + __expf(-(acc[mt][nt][2] + gv.x + bgv.x)));
                float s3 = 1.f / (1.f + __expf(-(acc[mt][nt][3] + gv.y + bgv.y)));
                float2 hv = *(const float2*)&hpbuf[lr1 * HPSTRIDE + col];
                *(float2*)&out[r1 * IN_DIM + col] =
                    make_float2(s2 * hv.x + (1.f - s2) * cv.x, s3 * hv.y + (1.f - s3) * cv.y);
            }
        }
    }
}

// ---------------- launch ----------------
#define SMEM_FEAT (4 * TILE_B)
#define SMEM_NODE (4 * TILE_B + 128 * HPSTRIDE * 4)

extern "C" void kernel_launch(void* const* d_in, const int* in_sizes, int n_in,
                              void* d_out, int out_size) {
    const float* h    = (const float*)d_in[0];
    const int*   src  = (const int*)d_in[1];
    const int*   dst  = (const int*)d_in[2];
    const float* ctx  = (const float*)d_in[3];
    const float* Wfc  = (const float*)d_in[4];
    const float* al   = (const float*)d_in[5];
    const float* ar   = (const float*)d_in[6];
    const float* bgat = (const float*)d_in[7];
    const float* Wp   = (const float*)d_in[8];
    const float* bp   = (const float*)d_in[9];
    const float* Wg   = (const float*)d_in[10];
    const float* bg   = (const float*)d_in[11];
    float* out = (float*)d_out;

    static int inited = 0;
    static cudaStream_t s1;
    static cudaEvent_t evA, evB, evC, evD;
    if (!inited) {
        cudaFuncSetAttribute(k_feat_tc, cudaFuncAttributeMaxDynamicSharedMemorySize, SMEM_FEAT);
        cudaFuncSetAttribute(k_ctxg, cudaFuncAttributeMaxDynamicSharedMemorySize, SMEM_FEAT);
        cudaFuncSetAttribute(k_node_tc, cudaFuncAttributeMaxDynamicSharedMemorySize, SMEM_NODE);
        cudaStreamCreateWithFlags(&s1, cudaStreamNonBlocking);
        cudaEventCreateWithFlags(&evA, cudaEventDisableTiming);
        cudaEventCreateWithFlags(&evB, cudaEventDisableTiming);
        cudaEventCreateWithFlags(&evC, cudaEventDisableTiming);
        cudaEventCreateWithFlags(&evD, cudaEventDisableTiming);
        inited = 1;
    }

    // fork
    cudaEventRecord(evA, 0);
    cudaStreamWaitEvent(s1, evA, 0);
    // s1: CSR build, then ctx-gate partial (after weights prepped)
    k_init<<<(NN + 255) / 256, 256, 0, s1>>>();
    k_hist<<<(EE + 255) / 256, 256, 0, s1>>>(dst);
    k_scan1<<<NBLK_SCAN, 256, 0, s1>>>();
    k_scan2<<<1, 256, 0, s1>>>();
    k_scatter<<<(EE + 255) / 256, 256, 0, s1>>>(src, dst);
    cudaEventRecord(evB, s1);

    // s0: weights, feat
    k_prepw<<<256, 256>>>(Wfc, Wp, Wg);
    cudaEventRecord(evC, 0);
    k_feat_tc<<<NCTA_GEMM, NTHR, SMEM_FEAT>>>(h, al, ar);

    // s1: ctxg after weights ready (runs concurrently with feat/agg)
    cudaStreamWaitEvent(s1, evC, 0);
    k_ctxg<<<NCTA_GEMM, NTHR, SMEM_FEAT, s1>>>(ctx);
    cudaEventRecord(evD, s1);

    // s0: join CSR, aggregate, then node (needs ctxg too)
    cudaStreamWaitEvent(0, evB, 0);
    k_agg<<<(NN * 32 + 255) / 256, 256>>>(bgat);
    cudaStreamWaitEvent(0, evD, 0);
    k_node_tc<<<NCTA_GEMM, NTHR, SMEM_NODE>>>(ctx, bp, bg, out);
}

// round 11
// speedup vs baseline: 1.5229x; 1.5229x over previous
#include <cuda_runtime.h>
#include <cuda_bf16.h>
#include <math.h>
#include <stdint.h>

#define NN 50000
#define EE 800000
#define IN_DIM 128
#define HH 4
#define NEG_SLOPE 0.2f
#define NBLK_SCAN 196
#define MTILE 128
#define NCTA_GEMM 391
#define TS 136
#define TILE_U16 (128 * TS)
#define TILE_B (TILE_U16 * 2)
#define NTHR 512

// ---------------- scratch ----------------
__device__ float g_feat[(size_t)NN * IN_DIM];
__device__ float g_el[NN * HH];
__device__ float g_er[NN * HH];
__device__ float g_hg[(size_t)NN * IN_DIM];
__device__ int   g_cnt[NN];
__device__ int   g_off[NN];
__device__ int   g_cur[NN];
__device__ int   g_esrc[EE];
__device__ int   g_bsum[256];
__device__ __align__(16) unsigned short g_WfcT[2 * TILE_U16];
__device__ __align__(16) unsigned short g_WpT[2 * TILE_U16];
__device__ __align__(16) unsigned short g_WgT[4 * TILE_U16];

// ---------------- helpers ----------------
__device__ __forceinline__ unsigned short bfb(__nv_bfloat16 v) {
    return *reinterpret_cast<unsigned short*>(&v);
}
__device__ __forceinline__ void split2(float x0, float x1, uint32_t& hi, uint32_t& lo) {
    __nv_bfloat16 h0 = __float2bfloat16(x0), h1 = __float2bfloat16(x1);
    __nv_bfloat16 l0 = __float2bfloat16(x0 - __bfloat162float(h0));
    __nv_bfloat16 l1 = __float2bfloat16(x1 - __bfloat162float(h1));
    hi = (uint32_t)bfb(h0) | ((uint32_t)bfb(h1) << 16);
    lo = (uint32_t)bfb(l0) | ((uint32_t)bfb(l1) << 16);
}
// reconstruct 2 fp32 from hi/lo bf16 tiles at u16 index idx (idx even)
__device__ __forceinline__ float2 recon2(const unsigned short* Hi, const unsigned short* Lo, int idx) {
    __nv_bfloat162 h = *(const __nv_bfloat162*)&Hi[idx];
    __nv_bfloat162 l = *(const __nv_bfloat162*)&Lo[idx];
    float2 hf = __bfloat1622float2(h);
    float2 lf = __bfloat1622float2(l);
    return make_float2(hf.x + lf.x, hf.y + lf.y);
}
__device__ __forceinline__ void hmma(float* c, uint32_t a0, uint32_t a1, uint32_t a2, uint32_t a3,
                                     uint32_t b0, uint32_t b1) {
    asm volatile(
        "mma.sync.aligned.m16n8k16.row.col.f32.bf16.bf16.f32 "
        "{%0,%1,%2,%3}, {%4,%5,%6,%7}, {%8,%9}, {%0,%1,%2,%3};"
        : "+f"(c[0]), "+f"(c[1]), "+f"(c[2]), "+f"(c[3])
        : "r"(a0), "r"(a1), "r"(a2), "r"(a3), "r"(b0), "r"(b1));
}

template <int NT>
__device__ __forceinline__ void gemm_tile(float acc[2][NT][4],
    const uint32_t* Ahi, const uint32_t* Alo,
    const uint32_t* Bhi, const uint32_t* Blo,
    int m0, int n0, int g, int t) {
#pragma unroll
    for (int ks = 0; ks < 8; ks++) {
        int k0 = ks * 16;
        uint32_t ah[2][4], al[2][4];
#pragma unroll
        for (int mt = 0; mt < 2; mt++) {
            int r = m0 + mt * 16 + g;
            int i0 = (r * TS + k0 + 2 * t) >> 1;
            int i1 = ((r + 8) * TS + k0 + 2 * t) >> 1;
            ah[mt][0] = Ahi[i0]; ah[mt][1] = Ahi[i1];
            ah[mt][2] = Ahi[i0 + 4]; ah[mt][3] = Ahi[i1 + 4];
            al[mt][0] = Alo[i0]; al[mt][1] = Alo[i1];
            al[mt][2] = Alo[i0 + 4]; al[mt][3] = Alo[i1 + 4];
        }
#pragma unroll
        for (int nt = 0; nt < NT; nt++) {
            int c = n0 + nt * 8 + g;
            int bi = (c * TS + k0 + 2 * t) >> 1;
            uint32_t bh0 = Bhi[bi], bh1 = Bhi[bi + 4];
            uint32_t bl0 = Blo[bi], bl1 = Blo[bi + 4];
#pragma unroll
            for (int mt = 0; mt < 2; mt++) {
                hmma(acc[mt][nt], ah[mt][0], ah[mt][1], ah[mt][2], ah[mt][3], bh0, bh1);
                hmma(acc[mt][nt], ah[mt][0], ah[mt][1], ah[mt][2], ah[mt][3], bl0, bl1);
                hmma(acc[mt][nt], al[mt][0], al[mt][1], al[mt][2], al[mt][3], bh0, bh1);
            }
        }
    }
}

__device__ __forceinline__ void fill_A(unsigned short* Ahi, unsigned short* Alo,
                                       const float* __restrict__ src, long nodebase,
                                       int tid) {
    int m = tid >> 2, q = tid & 3;
    long node = nodebase + m;
    const float* row = src + node * IN_DIM + q * 32;
    uint32_t* H = (uint32_t*)Ahi;
    uint32_t* L = (uint32_t*)Alo;
#pragma unroll
    for (int k4 = 0; k4 < 32; k4 += 4) {
        float4 v = make_float4(0.f, 0.f, 0.f, 0.f);
        if (node < NN) v = *(const float4*)(row + k4);
        uint32_t h01, l01, h23, l23;
        split2(v.x, v.y, h01, l01);
        split2(v.z, v.w, h23, l23);
        int idx = (m * TS + q * 32 + k4) >> 1;
        H[idx] = h01; H[idx + 1] = h23;
        L[idx] = l01; L[idx + 1] = l23;
    }
}

__device__ __forceinline__ void copy_B(unsigned short* dst, const unsigned short* src, int tid) {
    const uint4* s = (const uint4*)src;
    uint4* d = (uint4*)dst;
#pragma unroll
    for (int i = tid; i < 2 * TILE_B / 16; i += NTHR) d[i] = s[i];
}

// ---------------- small kernels ----------------
__global__ void k_init() {
    int i = blockIdx.x * blockDim.x + threadIdx.x;
    if (i < NN) { g_cnt[i] = 0; g_cur[i] = 0; }
}

__global__ void k_hist(const int* __restrict__ dst) {
    int e = blockIdx.x * blockDim.x + threadIdx.x;
    if (e < EE) atomicAdd(&g_cnt[dst[e]], 1);
}

// Wfc prep only (critical path for feat)
__global__ void k_prepw_fc(const float* __restrict__ Wfc) {
    int id = blockIdx.x * 256 + threadIdx.x;
    if (id >= 16384) return;
    int n = id >> 7, k = id & 127;
    float w = Wfc[k * 128 + n];
    __nv_bfloat16 hi = __float2bfloat16(w);
    __nv_bfloat16 lo = __float2bfloat16(w - __bfloat162float(hi));
    g_WfcT[n * TS + k] = bfb(hi);
    g_WfcT[TILE_U16 + n * TS + k] = bfb(lo);
}

// Wp + Wg prep (side stream, needed only by k_node)
__global__ void k_prepw_pg(const float* __restrict__ Wp, const float* __restrict__ Wg) {
    int id = blockIdx.x * 256 + threadIdx.x;   // 49152
    if (id < 16384) {
        int n = id >> 7, k = id & 127;
        float w = Wp[k * 128 + n];
        __nv_bfloat16 hi = __float2bfloat16(w);
        __nv_bfloat16 lo = __float2bfloat16(w - __bfloat162float(hi));
        g_WpT[n * TS + k] = bfb(hi);
        g_WpT[TILE_U16 + n * TS + k] = bfb(lo);
    } else if (id < 49152) {
        int e = id - 16384;          // 32768: n 0..127, k 0..255
        int n = e & 127, k = e >> 7;
        float w = Wg[k * 128 + n];
        int stage = k >> 7, kk = k & 127;
        __nv_bfloat16 hi = __float2bfloat16(w);
        __nv_bfloat16 lo = __float2bfloat16(w - __bfloat162float(hi));
        g_WgT[stage * 2 * TILE_U16 + n * TS + kk] = bfb(hi);
        g_WgT[stage * 2 * TILE_U16 + TILE_U16 + n * TS + kk] = bfb(lo);
    }
}

// ---------------- feat = h @ W_fc, fused el/er ----------------
__global__ void __launch_bounds__(NTHR, 1) k_feat_tc(const float* __restrict__ h,
                                                     const float* __restrict__ al,
                                                     const float* __restrict__ ar) {
    extern __shared__ __align__(16) unsigned short sm[];
    unsigned short* Ahi = sm;
    unsigned short* Alo = sm + TILE_U16;
    unsigned short* Bt  = sm + 2 * TILE_U16;
    int tid = threadIdx.x, wid = tid >> 5, lane = tid & 31;
    int g = lane >> 2, t = lane & 3;
    long nodebase = (long)blockIdx.x * MTILE;

    fill_A(Ahi, Alo, h, nodebase, tid);
    copy_B(Bt, g_WfcT, tid);
    __syncthreads();

    float acc[2][4][4];
#pragma unroll
    for (int a = 0; a < 2; a++)
#pragma unroll
        for (int b = 0; b < 4; b++)
#pragma unroll
            for (int c = 0; c < 4; c++) acc[a][b][c] = 0.f;

    int m0 = (wid >> 2) * 32, n0 = (wid & 3) * 32;
    gemm_tile<4>(acc, (const uint32_t*)Ahi, (const uint32_t*)Alo,
                 (const uint32_t*)Bt, (const uint32_t*)(Bt + TILE_U16), m0, n0, g, t);

    int head = wid & 3;
    float pl[4] = {0.f, 0.f, 0.f, 0.f};
    float pr[4] = {0.f, 0.f, 0.f, 0.f};
#pragma unroll
    for (int nt = 0; nt < 4; nt++) {
        int col = n0 + nt * 8 + 2 * t;
        float a0 = __ldg(&al[col]), a1 = __ldg(&al[col + 1]);
        float b0 = __ldg(&ar[col]), b1 = __ldg(&ar[col + 1]);
#pragma unroll
        for (int mt = 0; mt < 2; mt++) {
            pl[2 * mt]     += acc[mt][nt][0] * a0 + acc[mt][nt][1] * a1;
            pl[2 * mt + 1] += acc[mt][nt][2] * a0 + acc[mt][nt][3] * a1;
            pr[2 * mt]     += acc[mt][nt][0] * b0 + acc[mt][nt][1] * b1;
            pr[2 * mt + 1] += acc[mt][nt][2] * b0 + acc[mt][nt][3] * b1;
        }
    }
#pragma unroll
    for (int off = 1; off <= 2; off <<= 1) {
#pragma unroll
        for (int i = 0; i < 4; i++) {
            pl[i] += __shfl_xor_sync(0xffffffffu, pl[i], off);
            pr[i] += __shfl_xor_sync(0xffffffffu, pr[i], off);
        }
    }
    if (t == 0) {
#pragma unroll
        for (int mt = 0; mt < 2; mt++) {
            long r0 = nodebase + m0 + mt * 16 + g;
            long r1 = r0 + 8;
            if (r0 < NN) { g_el[r0 * HH + head] = pl[2 * mt];     g_er[r0 * HH + head] = pr[2 * mt]; }
            if (r1 < NN) { g_el[r1 * HH + head] = pl[2 * mt + 1]; g_er[r1 * HH + head] = pr[2 * mt + 1]; }
        }
    }

#pragma unroll
    for (int mt = 0; mt < 2; mt++) {
        long r0 = nodebase + m0 + mt * 16 + g;
        long r1 = r0 + 8;
#pragma unroll
        for (int nt = 0; nt < 4; nt++) {
            int col = n0 + nt * 8 + 2 * t;
            if (r0 < NN) *(float2*)&g_feat[r0 * IN_DIM + col] = make_float2(acc[mt][nt][0], acc[mt][nt][1]);
            if (r1 < NN) *(float2*)&g_feat[r1 * IN_DIM + col] = make_float2(acc[mt][nt][2], acc[mt][nt][3]);
        }
    }
}

// ---------------- scans / scatter ----------------
__global__ void k_scan1() {
    __shared__ int s[256];
    int i = blockIdx.x * 256 + threadIdx.x;
    int v = (i < NN) ? g_cnt[i] : 0;
    s[threadIdx.x] = v;
    __syncthreads();
#pragma unroll
    for (int off = 1; off < 256; off <<= 1) {
        int tv = (threadIdx.x >= off) ? s[threadIdx.x - off] : 0;
        __syncthreads();
        s[threadIdx.x] += tv;
        __syncthreads();
    }
    if (i < NN) g_off[i] = s[threadIdx.x] - v;
    if (threadIdx.x == 255) g_bsum[blockIdx.x] = s[255];
}

__global__ void k_scan2() {
    __shared__ int s[256];
    int t = threadIdx.x;
    int v = (t < NBLK_SCAN) ? g_bsum[t] : 0;
    s[t] = v;
    __syncthreads();
#pragma unroll
    for (int off = 1; off < 256; off <<= 1) {
        int tv = (t >= off) ? s[t - off] : 0;
        __syncthreads();
        s[t] += tv;
        __syncthreads();
    }
    if (t < NBLK_SCAN) g_bsum[t] = s[t] - v;
}

__global__ void k_scatter(const int* __restrict__ src, const int* __restrict__ dst) {
    int e = blockIdx.x * blockDim.x + threadIdx.x;
    if (e >= EE) return;
    int d = dst[e];
    int pos = atomicAdd(&g_cur[d], 1);
    g_esrc[g_off[d] + g_bsum[d >> 8] + pos] = src[e];
}

// ---------------- aggregate: warp per node, 4 edges/iter ----------------
__global__ void k_agg(const float* __restrict__ bgat) {
    int gw = (blockIdx.x * blockDim.x + threadIdx.x) >> 5;
    if (gw >= NN) return;
    int lane = threadIdx.x & 31;
    int beg = g_off[gw] + g_bsum[gw >> 8];
    int end = beg + g_cnt[gw];
    float er_h = (lane < HH) ? g_er[gw * HH + lane] : 0.f;
    float er16 = __shfl_sync(0xffffffffu, er_h, lane & 3);
    int hd = lane >> 3;
    float4 acc = make_float4(0.f, 0.f, 0.f, 0.f);
    float dsum = 0.f;
    int i = beg;
    for (; i + 3 < end; i += 4) {
        int s0 = __ldg(&g_esrc[i]);
        int s1 = __ldg(&g_esrc[i + 1]);
        int s2 = __ldg(&g_esrc[i + 2]);
        int s3 = __ldg(&g_esrc[i + 3]);
        float a = 0.f;
        if (lane < 16) {
            int eix = lane >> 2;
            int sx = (eix == 0) ? s0 : (eix == 1) ? s1 : (eix == 2) ? s2 : s3;
            float e = g_el[sx * HH + (lane & 3)] + er16;
            e = (e > 0.f) ? e : NEG_SLOPE * e;
            a = __expf(e);
        }
        float a0 = __shfl_sync(0xffffffffu, a, hd);
        float a1 = __shfl_sync(0xffffffffu, a, 4 + hd);
        float a2 = __shfl_sync(0xffffffffu, a, 8 + hd);
        float a3 = __shfl_sync(0xffffffffu, a, 12 + hd);
        dsum += (a0 + a1) + (a2 + a3);
        float4 f0 = ((const float4*)g_feat)[(size_t)s0 * (IN_DIM / 4) + lane];
        float4 f1 = ((const float4*)g_feat)[(size_t)s1 * (IN_DIM / 4) + lane];
        float4 f2 = ((const float4*)g_feat)[(size_t)s2 * (IN_DIM / 4) + lane];
        float4 f3 = ((const float4*)g_feat)[(size_t)s3 * (IN_DIM / 4) + lane];
        acc.x = fmaf(f0.x, a0, acc.x); acc.y = fmaf(f0.y, a0, acc.y);
        acc.z = fmaf(f0.z, a0, acc.z); acc.w = fmaf(f0.w, a0, acc.w);
        acc.x = fmaf(f1.x, a1, acc.x); acc.y = fmaf(f1.y, a1, acc.y);
        acc.z = fmaf(f1.z, a1, acc.z); acc.w = fmaf(f1.w, a1, acc.w);
        acc.x = fmaf(f2.x, a2, acc.x); acc.y = fmaf(f2.y, a2, acc.y);
        acc.z = fmaf(f2.z, a2, acc.z); acc.w = fmaf(f2.w, a2, acc.w);
        acc.x = fmaf(f3.x, a3, acc.x); acc.y = fmaf(f3.y, a3, acc.y);
        acc.z = fmaf(f3.z, a3, acc.z); acc.w = fmaf(f3.w, a3, acc.w);
    }
    for (; i < end; i++) {
        int s0 = __ldg(&g_esrc[i]);
        float a = 0.f;
        if (lane < 4) {
            float e = g_el[s0 * HH + lane] + er16;
            e = (e > 0.f) ? e : NEG_SLOPE * e;
            a = __expf(e);
        }
        float a0 = __shfl_sync(0xffffffffu, a, hd);
        dsum += a0;
        float4 f0 = ((const float4*)g_feat)[(size_t)s0 * (IN_DIM / 4) + lane];
        acc.x = fmaf(f0.x, a0, acc.x); acc.y = fmaf(f0.y, a0, acc.y);
        acc.z = fmaf(f0.z, a0, acc.z); acc.w = fmaf(f0.w, a0, acc.w);
    }
    float inv = (dsum > 0.f) ? (1.f / dsum) : 0.f;
    float4 b = ((const float4*)bgat)[lane];
    float4 o;
    o.x = acc.x * inv + b.x; o.y = acc.y * inv + b.y;
    o.z = acc.z * inv + b.z; o.w = acc.w * inv + b.w;
    o.x = (o.x > 0.f) ? o.x : expm1f(o.x);
    o.y = (o.y > 0.f) ? o.y : expm1f(o.y);
    o.z = (o.z > 0.f) ? o.z : expm1f(o.z);
    o.w = (o.w > 0.f) ? o.w : expm1f(o.w);
    ((float4*)g_hg)[(size_t)gw * (IN_DIM / 4) + lane] = o;
}

// ---------------- node: proj + gate + blend, 3-region smem ----------------
__global__ void __launch_bounds__(NTHR, 1) k_node_tc(
    const float* __restrict__ ctx, const float* __restrict__ bp,
    const float* __restrict__ bg, float* __restrict__ out) {
    extern __shared__ __align__(16) unsigned short sm[];
    unsigned short* Ahi = sm;                      // hg, then hp (split)
    unsigned short* Alo = sm + TILE_U16;
    unsigned short* Bt  = sm + 2 * TILE_U16;       // Wp -> Wg1 -> Wg2
    unsigned short* Chi = sm + 4 * TILE_U16;       // ctx (split), persistent
    unsigned short* Clo = sm + 5 * TILE_U16;
    int tid = threadIdx.x, wid = tid >> 5, lane = tid & 31;
    int g = lane >> 2, t = lane & 3;
    long nodebase = (long)blockIdx.x * MTILE;
    int m0 = (wid >> 2) * 32, n0 = (wid & 3) * 32;

    // fill everything needed up front
    fill_A(Ahi, Alo, g_hg, nodebase, tid);
    fill_A(Chi, Clo, ctx, nodebase, tid);
    copy_B(Bt, g_WpT, tid);
    __syncthreads();

    // phase 1: hp = hg @ Wp^T
    float acc[2][4][4];
#pragma unroll
    for (int a = 0; a < 2; a++)
#pragma unroll
        for (int b = 0; b < 4; b++)
#pragma unroll
            for (int c = 0; c < 4; c++) acc[a][b][c] = 0.f;

    gemm_tile<4>(acc, (const uint32_t*)Ahi, (const uint32_t*)Alo,
                 (const uint32_t*)Bt, (const uint32_t*)(Bt + TILE_U16), m0, n0, g, t);
    __syncthreads();

    // hp = acc + bias -> re-split into A tiles (also serves as epilogue hp source)
    {
        uint32_t* H = (uint32_t*)Ahi;
        uint32_t* L = (uint32_t*)Alo;
#pragma unroll
        for (int nt = 0; nt < 4; nt++) {
            int col = n0 + nt * 8 + 2 * t;
            float2 bpv = *(const float2*)&bp[col];
#pragma unroll
            for (int mt = 0; mt < 2; mt++) {
                int r0 = m0 + mt * 16 + g, r1 = r0 + 8;
                float h0 = acc[mt][nt][0] + bpv.x, h1 = acc[mt][nt][1] + bpv.y;
                float h2 = acc[mt][nt][2] + bpv.x, h3 = acc[mt][nt][3] + bpv.y;
                uint32_t hi, lo;
                split2(h0, h1, hi, lo);
                H[(r0 * TS + col) >> 1] = hi;
                L[(r0 * TS + col) >> 1] = lo;
                split2(h2, h3, hi, lo);
                H[(r1 * TS + col) >> 1] = hi;
                L[(r1 * TS + col) >> 1] = lo;
            }
        }
    }
    copy_B(Bt, g_WgT, tid);
    __syncthreads();

    // phase 2: gate = hp @ Wg1^T
#pragma unroll
    for (int a = 0; a < 2; a++)
#pragma unroll
        for (int b = 0; b < 4; b++)
#pragma unroll
            for (int c = 0; c < 4; c++) acc[a][b][c] = 0.f;
    gemm_tile<4>(acc, (const uint32_t*)Ahi, (const uint32_t*)Alo,
                 (const uint32_t*)Bt, (const uint32_t*)(Bt + TILE_U16), m0, n0, g, t);
    __syncthreads();

    // phase 3: gate += ctx @ Wg2^T  (ctx tiles already resident in region C)
    copy_B(Bt, g_WgT + 2 * TILE_U16, tid);
    __syncthreads();
    gemm_tile<4>(acc, (const uint32_t*)Chi, (const uint32_t*)Clo,
                 (const uint32_t*)Bt, (const uint32_t*)(Bt + TILE_U16), m0, n0, g, t);

    // epilogue: hp/ctx reconstructed from smem tiles (hi+lo), sigmoid, blend
#pragma unroll
    for (int nt = 0; nt < 4; nt++) {
        int col = n0 + nt * 8 + 2 * t;
        float2 bgv = *(const float2*)&bg[col];
#pragma unroll
        for (int mt = 0; mt < 2; mt++) {
            int lr0 = m0 + mt * 16 + g, lr1 = lr0 + 8;
            long r0 = nodebase + lr0, r1 = nodebase + lr1;
            if (r0 < NN) {
                float2 cv = recon2(Chi, Clo, lr0 * TS + col);
                float2 hv = recon2(Ahi, Alo, lr0 * TS + col);
                float s0 = 1.f / (1.f + __expf(-(acc[mt][nt][0] + bgv.x)));
                float s1 = 1.f / (1.f + __expf(-(acc[mt][nt][1] + bgv.y)));
                *(float2*)&out[r0 * IN_DIM + col] =
                    make_float2(s0 * hv.x + (1.f - s0) * cv.x, s1 * hv.y + (1.f - s1) * cv.y);
            }
            if (r1 < NN) {
                float2 cv = recon2(Chi, Clo, lr1 * TS + col);
                float2 hv = recon2(Ahi, Alo, lr1 * TS + col);
                float s2 = 1.f / (1.f + __expf(-(acc[mt][nt][2] + bgv.x)));
                float s3 = 1.f / (1.f + __expf(-(acc[mt][nt][3] + bgv.y)));
                *(float2*)&out[r1 * IN_DIM + col] =
                    make_float2(s2 * hv.x + (1.f - s2) * cv.x, s3 * hv.y + (1.f - s3) * cv.y);
            }
        }
    }
}

// ---------------- launch ----------------
#define SMEM_FEAT (4 * TILE_B)     // 139264
#define SMEM_NODE (6 * TILE_B)     // 208896

extern "C" void kernel_launch(void* const* d_in, const int* in_sizes, int n_in,
                              void* d_out, int out_size) {
    const float* h    = (const float*)d_in[0];
    const int*   src  = (const int*)d_in[1];
    const int*   dst  = (const int*)d_in[2];
    const float* ctx  = (const float*)d_in[3];
    const float* Wfc  = (const float*)d_in[4];
    const float* al   = (const float*)d_in[5];
    const float* ar   = (const float*)d_in[6];
    const float* bgat = (const float*)d_in[7];
    const float* Wp   = (const float*)d_in[8];
    const float* bp   = (const float*)d_in[9];
    const float* Wg   = (const float*)d_in[10];
    const float* bg   = (const float*)d_in[11];
    float* out = (float*)d_out;

    static int inited = 0;
    static cudaStream_t s1;
    static cudaEvent_t evA, evB;
    if (!inited) {
        cudaFuncSetAttribute(k_feat_tc, cudaFuncAttributeMaxDynamicSharedMemorySize, SMEM_FEAT);
        cudaFuncSetAttribute(k_node_tc, cudaFuncAttributeMaxDynamicSharedMemorySize, SMEM_NODE);
        cudaStreamCreateWithFlags(&s1, cudaStreamNonBlocking);
        cudaEventCreateWithFlags(&evA, cudaEventDisableTiming);
        cudaEventCreateWithFlags(&evB, cudaEventDisableTiming);
        inited = 1;
    }

    // fork: side stream does Wp/Wg prep + CSR build
    cudaEventRecord(evA, 0);
    cudaStreamWaitEvent(s1, evA, 0);
    k_prepw_pg<<<192, 256, 0, s1>>>(Wp, Wg);
    k_init<<<(NN + 255) / 256, 256, 0, s1>>>();
    k_hist<<<(EE + 255) / 256, 256, 0, s1>>>(dst);
    k_scan1<<<NBLK_SCAN, 256, 0, s1>>>();
    k_scan2<<<1, 256, 0, s1>>>();
    k_scatter<<<(EE + 255) / 256, 256, 0, s1>>>(src, dst);
    cudaEventRecord(evB, s1);

    // main: Wfc prep, feat
    k_prepw_fc<<<64, 256>>>(Wfc);
    k_feat_tc<<<NCTA_GEMM, NTHR, SMEM_FEAT>>>(h, al, ar);

    // join, aggregate, node
    cudaStreamWaitEvent(0, evB, 0);
    k_agg<<<(NN * 32 + 255) / 256, 256>>>(bgat);
    k_node_tc<<<NCTA_GEMM, NTHR, SMEM_NODE>>>(ctx, bp, bg, out);
}